// round 13
// baseline (speedup 1.0000x reference)
#include <cuda_runtime.h>
#include <cuda_fp16.h>
#include <cstdint>

// ---------------------------------------------------------------------------
// 6 chained GEMMs C = A @ W^T + b via single-pass fp16 mma.sync HMMA.
// R13: L2-bandwidth cut. Tile traffic ~ M*N*K*2*(1/BM+1/BN); 128x128 gave
// ~26GB L2-side (~2.3ms at LTS cap) co-binding with the 3.0ms tensor floor.
// Now BM=256, BN=128 (512 thr, 64 acc/thread, ~110 live regs, 1 CTA/SM):
// 25% less L2 + gmem->smem traffic, same per-SM tensor throughput.
// Loop keeps R11's proven order (compute THEN prefetch: the L1tex queue is a
// single in-order FIFO, so issuing cp.async before ldsm starves the MMAs).
// 3-stage pipeline, BKC=64, ROWB=144 conflict-free.
// ---------------------------------------------------------------------------

#define BM 256
#define BN 128
#define BKC 64
#define NTHR 512
#define ROWB 144u           // 64 fp16 = 128B data + 16B pad (9 x 16B units)
#define TILE_A 36864u       // 256 rows * 144B
#define TILE_W 18432u       // 128 rows * 144B
#define STG_BYTES 55296u    // A + W
#define NSTG 3
#define SMEM_SZ (NSTG * STG_BYTES)   // 165888

static const int T_TOK = 16384, HID = 2048, IMM = 4096;

// ---- scratch (__device__ globals; allocation-guard-safe) ----
__device__ __half g_wh[150994944];           // all weights fp16 (302 MB)
__device__ __half g_aA[67108864];            // 16384 x 4096 activations
__device__ __half g_aB[33554432];            // 16384 x 2048 activations

__device__ __forceinline__ uint32_t smem_u32(const void* p) {
    uint32_t a;
    asm("{ .reg .u64 t; cvta.to.shared.u64 t, %1; cvt.u32.u64 %0, t; }" : "=r"(a) : "l"(p));
    return a;
}
__device__ __forceinline__ void cp16(uint32_t dst, const void* src) {
    asm volatile("cp.async.cg.shared.global [%0], [%1], 16;" :: "r"(dst), "l"(src));
}
__device__ __forceinline__ void cp_commit() {
    asm volatile("cp.async.commit_group;" ::: "memory");
}
__device__ __forceinline__ void cp_wait2() {
    asm volatile("cp.async.wait_group 2;" ::: "memory");
}
__device__ __forceinline__ void ldsm4(uint32_t* r, uint32_t a) {
    asm volatile("ldmatrix.sync.aligned.m8n8.x4.shared.b16 {%0,%1,%2,%3}, [%4];"
                 : "=r"(r[0]), "=r"(r[1]), "=r"(r[2]), "=r"(r[3]) : "r"(a));
}
__device__ __forceinline__ void mma16816(float* d, const uint32_t* a, const uint32_t* b) {
    asm volatile("mma.sync.aligned.m16n8k16.row.col.f32.f16.f16.f32 "
                 "{%0,%1,%2,%3}, {%4,%5,%6,%7}, {%8,%9}, {%0,%1,%2,%3};"
                 : "+f"(d[0]), "+f"(d[1]), "+f"(d[2]), "+f"(d[3])
                 : "r"(a[0]), "r"(a[1]), "r"(a[2]), "r"(a[3]), "r"(b[0]), "r"(b[1]));
}

// ---- fp32 -> fp16 ----
__global__ void conv_h(const float4* __restrict__ in, __half* __restrict__ o, int n4)
{
    int i = blockIdx.x * blockDim.x + threadIdx.x;
    if (i >= n4) return;
    float4 v = in[i];
    uint2 p;
    p.x = (uint32_t)__half_as_ushort(__float2half(v.x))
        | ((uint32_t)__half_as_ushort(__float2half(v.y)) << 16);
    p.y = (uint32_t)__half_as_ushort(__float2half(v.z))
        | ((uint32_t)__half_as_ushort(__float2half(v.w)) << 16);
    ((uint2*)o)[i] = p;
}

// C[M,N] = A[M,K] @ W[N,K]^T + bias; grouped via blockIdx.z.
__global__ void __launch_bounds__(NTHR, 1)
gemm1p(const __half* __restrict__ A, const __half* __restrict__ W,
       const float* __restrict__ bias, float* __restrict__ Cf,
       __half* __restrict__ Ch,
       int M, int N, int K, int wantF32)
{
    extern __shared__ char smem[];
    const uint32_t sb = smem_u32(smem);

    const int tid  = threadIdx.x;
    const int lane = tid & 31;
    const int warp = tid >> 5;    // 0..15
    const int wm   = warp >> 2;   // 0..3 -> m offset 64
    const int wn   = warp & 3;    // 0..3 -> n offset 32
    const size_t g = blockIdx.z;
    const int n0 = blockIdx.x * BN;
    const int m0 = blockIdx.y * BM;

    const __half* Ag = A + g * (size_t)M * K + (size_t)m0 * K;
    const __half* Wg = W + g * (size_t)N * K + (size_t)n0 * K;

    // one stage = A(256 rows) + W(128 rows), 8 x 16B units per row; 6/thread
    auto load_stage = [&](int c, int s) {
        const uint32_t st = sb + (uint32_t)s * STG_BYTES;
        const size_t kof = (size_t)c * BKC;
        #pragma unroll
        for (int i = 0; i < 4; i++) {            // A: 2048 units
            int l = i * NTHR + tid;
            int row = l >> 3, c8 = l & 7;
            cp16(st + (uint32_t)row * ROWB + (uint32_t)c8 * 16,
                 Ag + (size_t)row * K + kof + c8 * 8);
        }
        #pragma unroll
        for (int i = 0; i < 2; i++) {            // W: 1024 units
            int l = i * NTHR + tid;
            int row = l >> 3, c8 = l & 7;
            cp16(st + TILE_A + (uint32_t)row * ROWB + (uint32_t)c8 * 16,
                 Wg + (size_t)row * K + kof + c8 * 8);
        }
        cp_commit();
    };

    float acc[4][4][4];
    #pragma unroll
    for (int mf = 0; mf < 4; mf++)
        #pragma unroll
        for (int nf = 0; nf < 4; nf++)
            #pragma unroll
            for (int q = 0; q < 4; q++) acc[mf][nf][q] = 0.f;

    const int KC = K / BKC;
    load_stage(0, 0);
    load_stage(1, 1);
    load_stage(2, 2);

    // ldmatrix base addresses (non-trans; both operands K-major)
    const uint32_t aRow = (uint32_t)(wm * 64 + (lane & 15)) * ROWB + (uint32_t)(lane >> 4) * 16;
    const uint32_t bRow = (uint32_t)(wn * 32 + ((lane >> 4) << 3) + (lane & 7)) * ROWB
                        + (uint32_t)((lane >> 3) & 1) * 16;

    int s = 0;
    for (int c = 0; c < KC; c++) {
        const uint32_t st = sb + (uint32_t)s * STG_BYTES;
        cp_wait2();
        __syncthreads();

        #pragma unroll
        for (int ks = 0; ks < 4; ks++) {
            const uint32_t ko = (uint32_t)ks * 32;  // 16 fp16 = 32B
            uint32_t a[4][4], b[2][4];
            #pragma unroll
            for (int mf = 0; mf < 4; mf++)
                ldsm4(a[mf], st + aRow + (uint32_t)mf * 16 * ROWB + ko);
            #pragma unroll
            for (int nf2 = 0; nf2 < 2; nf2++)
                ldsm4(b[nf2], st + TILE_A + bRow + (uint32_t)nf2 * 16 * ROWB + ko);
            #pragma unroll
            for (int mf = 0; mf < 4; mf++)
                #pragma unroll
                for (int nf2 = 0; nf2 < 2; nf2++) {
                    mma16816(acc[mf][2 * nf2],     a[mf], &b[nf2][0]);
                    mma16816(acc[mf][2 * nf2 + 1], a[mf], &b[nf2][2]);
                }
        }
        __syncthreads();
        if (c + NSTG < KC) load_stage(c + NSTG, s);
        else cp_commit();   // keep group-count invariant for cp_wait2
        s = (s + 1 == NSTG) ? 0 : s + 1;
    }

    // ---- epilogue ----
    const size_t co = g * (size_t)M * N;
    const float* bp = bias + g * N;
    #pragma unroll
    for (int mf = 0; mf < 4; mf++) {
        const int r0 = m0 + wm * 64 + mf * 16 + (lane >> 2);
        #pragma unroll
        for (int nf = 0; nf < 4; nf++) {
            const int cb = n0 + wn * 32 + nf * 8 + (lane & 3) * 2;
            const float b0 = bp[cb], b1 = bp[cb + 1];
            const float y00 = acc[mf][nf][0] + b0, y01 = acc[mf][nf][1] + b1;
            const float y10 = acc[mf][nf][2] + b0, y11 = acc[mf][nf][3] + b1;
            const size_t o0 = co + (size_t)r0 * N + cb;
            const size_t o1 = co + (size_t)(r0 + 8) * N + cb;
            if (wantF32) {
                *(float2*)(Cf + o0) = make_float2(y00, y01);
                *(float2*)(Cf + o1) = make_float2(y10, y11);
            } else {
                *(uint32_t*)(Ch + o0) =
                    (uint32_t)__half_as_ushort(__float2half(y00))
                  | ((uint32_t)__half_as_ushort(__float2half(y01)) << 16);
                *(uint32_t*)(Ch + o1) =
                    (uint32_t)__half_as_ushort(__float2half(y10))
                  | ((uint32_t)__half_as_ushort(__float2half(y11)) << 16);
            }
        }
    }
}

// ---------------------------------------------------------------------------
extern "C" void kernel_launch(void* const* d_in, const int* in_sizes, int n_in,
                              void* d_out, int out_size)
{
    (void)in_sizes; (void)n_in; (void)out_size;
    const float* x  = (const float*)d_in[0];
    const float* w1 = (const float*)d_in[1];
    const float* b1 = (const float*)d_in[2];
    const float* w2 = (const float*)d_in[3];
    const float* b2 = (const float*)d_in[4];
    const float* g1w[2] = { (const float*)d_in[5],  (const float*)d_in[9]  };
    const float* g1b[2] = { (const float*)d_in[6],  (const float*)d_in[10] };
    const float* g2w[2] = { (const float*)d_in[7],  (const float*)d_in[11] };
    const float* g2b[2] = { (const float*)d_in[8],  (const float*)d_in[12] };
    float* out = (float*)d_out;

    __half *wh, *aA, *aB;
    cudaGetSymbolAddress((void**)&wh, g_wh);
    cudaGetSymbolAddress((void**)&aA, g_aA);
    cudaGetSymbolAddress((void**)&aB, g_aB);

    const size_t OW1 = 0, OW2 = 8388608;
    const size_t OG[4] = { 16777216, 50331648, 83886080, 117440512 };

    cudaFuncSetAttribute(gemm1p, cudaFuncAttributeMaxDynamicSharedMemorySize, SMEM_SZ);

    auto conv = [&](const float* src, __half* dst, size_t n) {
        int n4 = (int)(n / 4);
        conv_h<<<(n4 + 255) / 256, 256>>>((const float4*)src, dst, n4);
    };

    const int Mg = T_TOK / 4;
    dim3 blk(NTHR);

    conv(x,      aB,         (size_t)T_TOK * HID);
    conv(w1,     wh + OW1,   (size_t)IMM * HID);
    conv(w2,     wh + OW2,   (size_t)HID * IMM);
    conv(g1w[0], wh + OG[0], (size_t)4 * IMM * HID);
    conv(g2w[0], wh + OG[1], (size_t)4 * HID * IMM);

    // x @ w1^T -> actA  [16384, 4096]
    gemm1p<<<dim3(IMM / BN, T_TOK / BM, 1), blk, SMEM_SZ>>>(
        aB, wh + OW1, b1, nullptr, aA, T_TOK, IMM, HID, 0);

    conv(g1w[1], wh + OG[2], (size_t)4 * IMM * HID);
    conv(g2w[1], wh + OG[3], (size_t)4 * HID * IMM);

    // actA @ w2^T -> actB  [16384, 2048]
    gemm1p<<<dim3(HID / BN, T_TOK / BM, 1), blk, SMEM_SZ>>>(
        aA, wh + OW2, b2, nullptr, aB, T_TOK, HID, IMM, 0);
    // two grouped-MLP layers
    for (int li = 0; li < 2; li++) {
        gemm1p<<<dim3(IMM / BN, Mg / BM, 4), blk, SMEM_SZ>>>(
            aB, wh + OG[2 * li], g1b[li], nullptr, aA, Mg, IMM, HID, 0);
        int fin = (li == 1);
        gemm1p<<<dim3(HID / BN, Mg / BM, 4), blk, SMEM_SZ>>>(
            aA, wh + OG[2 * li + 1], g2b[li],
            fin ? out : nullptr, aB, Mg, HID, IMM, fin);
    }
}

// round 15
// speedup vs baseline: 1.1584x; 1.1584x over previous
#include <cuda_runtime.h>
#include <cuda_fp16.h>
#include <cstdint>

// ---------------------------------------------------------------------------
// 6 chained GEMMs C = A @ W^T + b via single-pass fp16 mma.sync HMMA.
// R14 = R11 (best: 4314us; 128x128 tile, 8 warps of 64x32, 2 CTAs/SM,
// 3-stage cp.async, BKC=64, compute-then-prefetch order) + register-level
// fragment double buffering: ldsm for ks+1 issued before the MMAs of ks,
// hiding the 29cyc LDS latency + crossbar time (75% of tensor time) under
// the HMMA burst. Only change vs R11 -- isolates the scheduling effect.
// ---------------------------------------------------------------------------

#define BM 128
#define BN 128
#define BKC 64
#define ROWB 144u           // 64 fp16 = 128B data + 16B pad (9 x 16B units)
#define TILE_B 18432u       // 128 rows * 144B
#define STG_BYTES 36864u    // A + W (2 tiles)
#define NSTG 3
#define SMEM_SZ (NSTG * STG_BYTES)

static const int T_TOK = 16384, HID = 2048, IMM = 4096;

// ---- scratch (__device__ globals; allocation-guard-safe) ----
__device__ __half g_wh[150994944];           // all weights fp16 (302 MB)
__device__ __half g_aA[67108864];            // 16384 x 4096 activations
__device__ __half g_aB[33554432];            // 16384 x 2048 activations

__device__ __forceinline__ uint32_t smem_u32(const void* p) {
    uint32_t a;
    asm("{ .reg .u64 t; cvta.to.shared.u64 t, %1; cvt.u32.u64 %0, t; }" : "=r"(a) : "l"(p));
    return a;
}
__device__ __forceinline__ void cp16(uint32_t dst, const void* src) {
    asm volatile("cp.async.cg.shared.global [%0], [%1], 16;" :: "r"(dst), "l"(src));
}
__device__ __forceinline__ void cp_commit() {
    asm volatile("cp.async.commit_group;" ::: "memory");
}
__device__ __forceinline__ void cp_wait2() {
    asm volatile("cp.async.wait_group 2;" ::: "memory");
}
__device__ __forceinline__ void ldsm4(uint32_t* r, uint32_t a) {
    asm volatile("ldmatrix.sync.aligned.m8n8.x4.shared.b16 {%0,%1,%2,%3}, [%4];"
                 : "=r"(r[0]), "=r"(r[1]), "=r"(r[2]), "=r"(r[3]) : "r"(a));
}
__device__ __forceinline__ void mma16816(float* d, const uint32_t* a, const uint32_t* b) {
    asm volatile("mma.sync.aligned.m16n8k16.row.col.f32.f16.f16.f32 "
                 "{%0,%1,%2,%3}, {%4,%5,%6,%7}, {%8,%9}, {%0,%1,%2,%3};"
                 : "+f"(d[0]), "+f"(d[1]), "+f"(d[2]), "+f"(d[3])
                 : "r"(a[0]), "r"(a[1]), "r"(a[2]), "r"(a[3]), "r"(b[0]), "r"(b[1]));
}

// ---- fp32 -> fp16 ----
__global__ void conv_h(const float4* __restrict__ in, __half* __restrict__ o, int n4)
{
    int i = blockIdx.x * blockDim.x + threadIdx.x;
    if (i >= n4) return;
    float4 v = in[i];
    uint2 p;
    p.x = (uint32_t)__half_as_ushort(__float2half(v.x))
        | ((uint32_t)__half_as_ushort(__float2half(v.y)) << 16);
    p.y = (uint32_t)__half_as_ushort(__float2half(v.z))
        | ((uint32_t)__half_as_ushort(__float2half(v.w)) << 16);
    ((uint2*)o)[i] = p;
}

// C[M,N] = A[M,K] @ W[N,K]^T + bias; grouped via blockIdx.z.
__global__ void __launch_bounds__(256, 2)
gemm1p(const __half* __restrict__ A, const __half* __restrict__ W,
       const float* __restrict__ bias, float* __restrict__ Cf,
       __half* __restrict__ Ch,
       int M, int N, int K, int wantF32)
{
    extern __shared__ char smem[];
    const uint32_t sb = smem_u32(smem);

    const int tid  = threadIdx.x;
    const int lane = tid & 31;
    const int warp = tid >> 5;
    const int wm   = warp >> 2;   // 0..1 -> m offset 64
    const int wn   = warp & 3;    // 0..3 -> n offset 32
    const size_t g = blockIdx.z;
    const int n0 = blockIdx.x * BN;
    const int m0 = blockIdx.y * BM;

    const __half* Ag = A + g * (size_t)M * K + (size_t)m0 * K;
    const __half* Wg = W + g * (size_t)N * K + (size_t)n0 * K;

    // one stage = 2 tiles x 128 rows x 8 units = 2048 cp16; 8 per thread
    auto load_stage = [&](int c, int s) {
        const uint32_t st = sb + (uint32_t)s * STG_BYTES;
        const size_t kof = (size_t)c * BKC;
        #pragma unroll
        for (int i = 0; i < 8; i++) {
            int l = i * 256 + tid;
            const __half* src;
            uint32_t base;
            int t;
            if (i < 4) { t = l;        src = Ag; base = st; }
            else       { t = l - 1024; src = Wg; base = st + TILE_B; }
            int row = t >> 3, c8 = t & 7;
            cp16(base + (uint32_t)row * ROWB + (uint32_t)c8 * 16,
                 src + (size_t)row * K + kof + c8 * 8);
        }
        cp_commit();
    };

    float acc[4][4][4];
    #pragma unroll
    for (int mf = 0; mf < 4; mf++)
        #pragma unroll
        for (int nf = 0; nf < 4; nf++)
            #pragma unroll
            for (int q = 0; q < 4; q++) acc[mf][nf][q] = 0.f;

    const int KC = K / BKC;
    load_stage(0, 0);
    load_stage(1, 1);
    load_stage(2, 2);

    // ldmatrix base addresses (non-trans; both operands K-major)
    const uint32_t aRow = (uint32_t)(wm * 64 + (lane & 15)) * ROWB + (uint32_t)(lane >> 4) * 16;
    const uint32_t bRow = (uint32_t)(wn * 32 + ((lane >> 4) << 3) + (lane & 7)) * ROWB
                        + (uint32_t)((lane >> 3) & 1) * 16;

    int s = 0;
    for (int c = 0; c < KC; c++) {
        const uint32_t st = sb + (uint32_t)s * STG_BYTES;
        cp_wait2();
        __syncthreads();

        uint32_t af[2][4][4], bf[2][2][4];
        // prime ks=0 fragments
        #pragma unroll
        for (int mf = 0; mf < 4; mf++)
            ldsm4(af[0][mf], st + aRow + (uint32_t)mf * 16 * ROWB);
        #pragma unroll
        for (int nf2 = 0; nf2 < 2; nf2++)
            ldsm4(bf[0][nf2], st + TILE_B + bRow + (uint32_t)nf2 * 16 * ROWB);

        #pragma unroll
        for (int ks = 0; ks < 4; ks++) {
            const int cur = ks & 1, nxt = cur ^ 1;
            if (ks < 3) {           // issue next-ks ldsm BEFORE this ks's MMAs
                const uint32_t ko = (uint32_t)(ks + 1) * 32;
                #pragma unroll
                for (int mf = 0; mf < 4; mf++)
                    ldsm4(af[nxt][mf], st + aRow + (uint32_t)mf * 16 * ROWB + ko);
                #pragma unroll
                for (int nf2 = 0; nf2 < 2; nf2++)
                    ldsm4(bf[nxt][nf2], st + TILE_B + bRow + (uint32_t)nf2 * 16 * ROWB + ko);
            }
            #pragma unroll
            for (int mf = 0; mf < 4; mf++)
                #pragma unroll
                for (int nf2 = 0; nf2 < 2; nf2++) {
                    mma16816(acc[mf][2 * nf2],     af[cur][mf], &bf[cur][nf2][0]);
                    mma16816(acc[mf][2 * nf2 + 1], af[cur][mf], &bf[cur][nf2][2]);
                }
        }
        __syncthreads();
        if (c + NSTG < KC) load_stage(c + NSTG, s);
        else cp_commit();   // keep group-count invariant for cp_wait2
        s = (s + 1 == NSTG) ? 0 : s + 1;
    }

    // ---- epilogue ----
    const size_t co = g * (size_t)M * N;
    const float* bp = bias + g * N;
    #pragma unroll
    for (int mf = 0; mf < 4; mf++) {
        const int r0 = m0 + wm * 64 + mf * 16 + (lane >> 2);
        #pragma unroll
        for (int nf = 0; nf < 4; nf++) {
            const int cb = n0 + wn * 32 + nf * 8 + (lane & 3) * 2;
            const float b0 = bp[cb], b1 = bp[cb + 1];
            const float y00 = acc[mf][nf][0] + b0, y01 = acc[mf][nf][1] + b1;
            const float y10 = acc[mf][nf][2] + b0, y11 = acc[mf][nf][3] + b1;
            const size_t o0 = co + (size_t)r0 * N + cb;
            const size_t o1 = co + (size_t)(r0 + 8) * N + cb;
            if (wantF32) {
                *(float2*)(Cf + o0) = make_float2(y00, y01);
                *(float2*)(Cf + o1) = make_float2(y10, y11);
            } else {
                *(uint32_t*)(Ch + o0) =
                    (uint32_t)__half_as_ushort(__float2half(y00))
                  | ((uint32_t)__half_as_ushort(__float2half(y01)) << 16);
                *(uint32_t*)(Ch + o1) =
                    (uint32_t)__half_as_ushort(__float2half(y10))
                  | ((uint32_t)__half_as_ushort(__float2half(y11)) << 16);
            }
        }
    }
}

// ---------------------------------------------------------------------------
extern "C" void kernel_launch(void* const* d_in, const int* in_sizes, int n_in,
                              void* d_out, int out_size)
{
    (void)in_sizes; (void)n_in; (void)out_size;
    const float* x  = (const float*)d_in[0];
    const float* w1 = (const float*)d_in[1];
    const float* b1 = (const float*)d_in[2];
    const float* w2 = (const float*)d_in[3];
    const float* b2 = (const float*)d_in[4];
    const float* g1w[2] = { (const float*)d_in[5],  (const float*)d_in[9]  };
    const float* g1b[2] = { (const float*)d_in[6],  (const float*)d_in[10] };
    const float* g2w[2] = { (const float*)d_in[7],  (const float*)d_in[11] };
    const float* g2b[2] = { (const float*)d_in[8],  (const float*)d_in[12] };
    float* out = (float*)d_out;

    __half *wh, *aA, *aB;
    cudaGetSymbolAddress((void**)&wh, g_wh);
    cudaGetSymbolAddress((void**)&aA, g_aA);
    cudaGetSymbolAddress((void**)&aB, g_aB);

    const size_t OW1 = 0, OW2 = 8388608;
    const size_t OG[4] = { 16777216, 50331648, 83886080, 117440512 };

    cudaFuncSetAttribute(gemm1p, cudaFuncAttributeMaxDynamicSharedMemorySize, SMEM_SZ);

    auto conv = [&](const float* src, __half* dst, size_t n) {
        int n4 = (int)(n / 4);
        conv_h<<<(n4 + 255) / 256, 256>>>((const float4*)src, dst, n4);
    };

    const int Mg = T_TOK / 4;
    dim3 blk(256);

    conv(x,      aB,         (size_t)T_TOK * HID);
    conv(w1,     wh + OW1,   (size_t)IMM * HID);
    conv(w2,     wh + OW2,   (size_t)HID * IMM);
    conv(g1w[0], wh + OG[0], (size_t)4 * IMM * HID);
    conv(g2w[0], wh + OG[1], (size_t)4 * HID * IMM);

    // x @ w1^T -> actA  [16384, 4096]
    gemm1p<<<dim3(IMM / BN, T_TOK / BM, 1), blk, SMEM_SZ>>>(
        aB, wh + OW1, b1, nullptr, aA, T_TOK, IMM, HID, 0);

    conv(g1w[1], wh + OG[2], (size_t)4 * IMM * HID);
    conv(g2w[1], wh + OG[3], (size_t)4 * HID * IMM);

    // actA @ w2^T -> actB  [16384, 2048]
    gemm1p<<<dim3(HID / BN, T_TOK / BM, 1), blk, SMEM_SZ>>>(
        aA, wh + OW2, b2, nullptr, aB, T_TOK, HID, IMM, 0);
    // two grouped-MLP layers
    for (int li = 0; li < 2; li++) {
        gemm1p<<<dim3(IMM / BN, Mg / BM, 4), blk, SMEM_SZ>>>(
            aB, wh + OG[2 * li], g1b[li], nullptr, aA, Mg, IMM, HID, 0);
        int fin = (li == 1);
        gemm1p<<<dim3(HID / BN, Mg / BM, 4), blk, SMEM_SZ>>>(
            aA, wh + OG[2 * li + 1], g2b[li],
            fin ? out : nullptr, aB, Mg, HID, IMM, fin);
    }
}

// round 16
// speedup vs baseline: 1.4410x; 1.2439x over previous
#include <cuda.h>
#include <cuda_runtime.h>
#include <cuda_fp16.h>
#include <cstdint>

// ---------------------------------------------------------------------------
// 6 chained GEMMs C = A @ W^T + b via single-pass fp16 mma.sync HMMA.
// R16: TMA producer path. R12/R13/R14 all plateaued at ~4.3-4.5ms =>
// binding resource is the cp.async produce path (2048 L1tex wavefronts +
// 1024 issue slots per SM-chunk) co-binding with the HMMA pipe. Replace it
// with cp.async.bulk.tensor.2d (sm_90 baseline PTX) + mbarrier expect_tx:
// 2 TMA ops/chunk issued by one thread; SW128 tensormap keeps ldsm
// conflict-free (lane unit ^= row&7). Compute structure = R11 verbatim.
// CTA 128x128, 8 warps of 64x32, 2 CTAs/SM, 3 stages, BKC=64.
// ---------------------------------------------------------------------------

#define BM 128
#define BN 128
#define BKC 64
#define TILE_B 16384u       // one 128x64 fp16 tile, SW128, no padding
#define STG_BYTES 32768u    // A + W
#define NSTG 3
#define SMEM_SZ (NSTG * STG_BYTES + 1024)   // + alignment slack

static const int T_TOK = 16384, HID = 2048, IMM = 4096;

// ---- scratch (__device__ globals; allocation-guard-safe) ----
__device__ __half g_wh[150994944];           // all weights fp16 (302 MB)
__device__ __half g_aA[67108864];            // 16384 x 4096 activations
__device__ __half g_aB[33554432];            // 16384 x 2048 activations

__device__ __forceinline__ uint32_t smem_u32(const void* p) {
    uint32_t a;
    asm("{ .reg .u64 t; cvta.to.shared.u64 t, %1; cvt.u32.u64 %0, t; }" : "=r"(a) : "l"(p));
    return a;
}
__device__ __forceinline__ void ldsm4(uint32_t* r, uint32_t a) {
    asm volatile("ldmatrix.sync.aligned.m8n8.x4.shared.b16 {%0,%1,%2,%3}, [%4];"
                 : "=r"(r[0]), "=r"(r[1]), "=r"(r[2]), "=r"(r[3]) : "r"(a));
}
__device__ __forceinline__ void mma16816(float* d, const uint32_t* a, const uint32_t* b) {
    asm volatile("mma.sync.aligned.m16n8k16.row.col.f32.f16.f16.f32 "
                 "{%0,%1,%2,%3}, {%4,%5,%6,%7}, {%8,%9}, {%0,%1,%2,%3};"
                 : "+f"(d[0]), "+f"(d[1]), "+f"(d[2]), "+f"(d[3])
                 : "r"(a[0]), "r"(a[1]), "r"(a[2]), "r"(a[3]), "r"(b[0]), "r"(b[1]));
}
__device__ __forceinline__ void mbar_init(uint32_t a, uint32_t cnt) {
    asm volatile("mbarrier.init.shared.b64 [%0], %1;" :: "r"(a), "r"(cnt) : "memory");
}
__device__ __forceinline__ void mbar_expect_tx(uint32_t a, uint32_t bytes) {
    asm volatile("mbarrier.arrive.expect_tx.shared.b64 _, [%0], %1;"
                 :: "r"(a), "r"(bytes) : "memory");
}
__device__ __forceinline__ void mbar_wait(uint32_t a, uint32_t parity) {
    asm volatile("{\n\t.reg .pred P;\n\tWL_%=:\n\t"
                 "mbarrier.try_wait.parity.acquire.cta.shared::cta.b64 P, [%0], %1;\n\t"
                 "@!P bra WL_%=;\n\t}" :: "r"(a), "r"(parity) : "memory");
}
__device__ __forceinline__ void tma2d(uint32_t dst, const CUtensorMap* tm,
                                      int cx, int cy, uint32_t mbar) {
    asm volatile("cp.async.bulk.tensor.2d.shared::cta.global.tile.mbarrier::complete_tx::bytes "
                 "[%0], [%1, {%2, %3}], [%4];"
                 :: "r"(dst), "l"(tm), "r"(cx), "r"(cy), "r"(mbar) : "memory");
}

// ---- fp32 -> fp16 ----
__global__ void conv_h(const float4* __restrict__ in, __half* __restrict__ o, int n4)
{
    int i = blockIdx.x * blockDim.x + threadIdx.x;
    if (i >= n4) return;
    float4 v = in[i];
    uint2 p;
    p.x = (uint32_t)__half_as_ushort(__float2half(v.x))
        | ((uint32_t)__half_as_ushort(__float2half(v.y)) << 16);
    p.y = (uint32_t)__half_as_ushort(__float2half(v.z))
        | ((uint32_t)__half_as_ushort(__float2half(v.w)) << 16);
    ((uint2*)o)[i] = p;
}

// C[M,N] = A[M,K] @ W[N,K]^T + bias; grouped via blockIdx.z (contiguous slabs
// in both the A-activation tensor [G*M,K] and weight tensor [G*N,K]).
__global__ void __launch_bounds__(256, 2)
gemm1p(const __grid_constant__ CUtensorMap tmA,
       const __grid_constant__ CUtensorMap tmW,
       const float* __restrict__ bias, float* __restrict__ Cf,
       __half* __restrict__ Ch,
       int M, int N, int K, int wantF32)
{
    extern __shared__ char smraw[];
    const uint32_t sbr = smem_u32(smraw);
    const uint32_t sb = (sbr + 1023u) & ~1023u;    // 1KB-align for SW128
    __shared__ __align__(8) uint64_t mbar_store[NSTG];
    const uint32_t mb = smem_u32(mbar_store);

    const int tid  = threadIdx.x;
    const int lane = tid & 31;
    const int warp = tid >> 5;
    const int wm   = warp >> 2;   // 0..1 -> m offset 64
    const int wn   = warp & 3;    // 0..3 -> n offset 32
    const int g  = blockIdx.z;
    const int n0 = blockIdx.x * BN;                 // group-local col base
    const int mBase = g * M + blockIdx.y * BM;      // tensor row base (A)
    const int nBase = g * N + n0;                   // tensor row base (W)

    if (tid == 0) {
        #pragma unroll
        for (int s = 0; s < NSTG; s++) mbar_init(mb + 8u * s, 1);
        asm volatile("fence.proxy.async.shared::cta;" ::: "memory");
    }
    __syncthreads();

    const int KC = K / BKC;
    if (tid == 0) {
        #pragma unroll
        for (int s = 0; s < NSTG; s++) {
            mbar_expect_tx(mb + 8u * s, STG_BYTES);
            tma2d(sb + s * STG_BYTES,          &tmA, s * BKC, mBase, mb + 8u * s);
            tma2d(sb + s * STG_BYTES + TILE_B, &tmW, s * BKC, nBase, mb + 8u * s);
        }
    }

    float acc[4][4][4];
    #pragma unroll
    for (int mf = 0; mf < 4; mf++)
        #pragma unroll
        for (int nf = 0; nf < 4; nf++)
            #pragma unroll
            for (int q = 0; q < 4; q++) acc[mf][nf][q] = 0.f;

    // ldsm lane geometry (SW128: 16B-unit index XORed with row&7)
    const uint32_t rA0 = (uint32_t)(wm * 64 + (lane & 15));          // + mf*16
    const uint32_t rB0 = (uint32_t)(wn * 32 + ((lane >> 4) << 3) + (lane & 7)); // + nf2*16
    const uint32_t rm  = (uint32_t)(lane & 7);   // row&7 for both (offsets mult of 8/16)
    const uint32_t uA0 = (uint32_t)(lane >> 4);
    const uint32_t uB0 = (uint32_t)((lane >> 3) & 1);

    int s = 0;
    for (int c = 0; c < KC; c++) {
        const uint32_t st = sb + (uint32_t)s * STG_BYTES;
        mbar_wait(mb + 8u * s, (uint32_t)((c / NSTG) & 1));

        #pragma unroll
        for (int ks = 0; ks < 4; ks++) {
            const uint32_t ua = ((uA0 + 2u * ks) ^ rm) * 16u;
            const uint32_t ub = ((uB0 + 2u * ks) ^ rm) * 16u;
            uint32_t a[4][4], b[2][4];
            #pragma unroll
            for (int mf = 0; mf < 4; mf++)
                ldsm4(a[mf], st + (rA0 + mf * 16u) * 128u + ua);
            #pragma unroll
            for (int nf2 = 0; nf2 < 2; nf2++)
                ldsm4(b[nf2], st + TILE_B + (rB0 + nf2 * 16u) * 128u + ub);
            #pragma unroll
            for (int mf = 0; mf < 4; mf++)
                #pragma unroll
                for (int nf2 = 0; nf2 < 2; nf2++) {
                    mma16816(acc[mf][2 * nf2],     a[mf], &b[nf2][0]);
                    mma16816(acc[mf][2 * nf2 + 1], a[mf], &b[nf2][2]);
                }
        }
        __syncthreads();          // all warps done reading slot s
        if (tid == 0 && c + NSTG < KC) {
            mbar_expect_tx(mb + 8u * s, STG_BYTES);
            tma2d(st,          &tmA, (c + NSTG) * BKC, mBase, mb + 8u * s);
            tma2d(st + TILE_B, &tmW, (c + NSTG) * BKC, nBase, mb + 8u * s);
        }
        s = (s + 1 == NSTG) ? 0 : s + 1;
    }

    // ---- epilogue ----
    const float* bp = bias + (size_t)g * N;
    #pragma unroll
    for (int mf = 0; mf < 4; mf++) {
        const int rg = mBase + wm * 64 + mf * 16 + (lane >> 2);   // global C row
        #pragma unroll
        for (int nf = 0; nf < 4; nf++) {
            const int cb = n0 + wn * 32 + nf * 8 + (lane & 3) * 2;
            const float b0 = bp[cb], b1 = bp[cb + 1];
            const float y00 = acc[mf][nf][0] + b0, y01 = acc[mf][nf][1] + b1;
            const float y10 = acc[mf][nf][2] + b0, y11 = acc[mf][nf][3] + b1;
            const size_t o0 = (size_t)rg * N + cb;
            const size_t o1 = (size_t)(rg + 8) * N + cb;
            if (wantF32) {
                *(float2*)(Cf + o0) = make_float2(y00, y01);
                *(float2*)(Cf + o1) = make_float2(y10, y11);
            } else {
                *(uint32_t*)(Ch + o0) =
                    (uint32_t)__half_as_ushort(__float2half(y00))
                  | ((uint32_t)__half_as_ushort(__float2half(y01)) << 16);
                *(uint32_t*)(Ch + o1) =
                    (uint32_t)__half_as_ushort(__float2half(y10))
                  | ((uint32_t)__half_as_ushort(__float2half(y11)) << 16);
            }
        }
    }
}

// ---------------------------------------------------------------------------
typedef CUresult (*PFN_encodeTiled)(
    CUtensorMap*, CUtensorMapDataType, cuuint32_t, void*,
    const cuuint64_t*, const cuuint64_t*, const cuuint32_t*, const cuuint32_t*,
    CUtensorMapInterleave, CUtensorMapSwizzle, CUtensorMapL2promotion,
    CUtensorMapFloatOOBfill);

static CUtensorMap mk2d(PFN_encodeTiled enc, void* p, uint64_t d0, uint64_t d1)
{
    CUtensorMap m{};
    cuuint64_t dims[2]    = { d0, d1 };
    cuuint64_t strides[1] = { d0 * 2 };             // fp16 row pitch (bytes)
    cuuint32_t box[2]     = { 64u, 128u };          // 128B x 128 rows
    cuuint32_t es[2]      = { 1u, 1u };
    enc(&m, CU_TENSOR_MAP_DATA_TYPE_FLOAT16, 2, p, dims, strides, box, es,
        CU_TENSOR_MAP_INTERLEAVE_NONE, CU_TENSOR_MAP_SWIZZLE_128B,
        CU_TENSOR_MAP_L2_PROMOTION_L2_128B, CU_TENSOR_MAP_FLOAT_OOB_FILL_NONE);
    return m;
}

extern "C" void kernel_launch(void* const* d_in, const int* in_sizes, int n_in,
                              void* d_out, int out_size)
{
    (void)in_sizes; (void)n_in; (void)out_size;
    const float* x  = (const float*)d_in[0];
    const float* w1 = (const float*)d_in[1];
    const float* b1 = (const float*)d_in[2];
    const float* w2 = (const float*)d_in[3];
    const float* b2 = (const float*)d_in[4];
    const float* g1w[2] = { (const float*)d_in[5],  (const float*)d_in[9]  };
    const float* g1b[2] = { (const float*)d_in[6],  (const float*)d_in[10] };
    const float* g2w[2] = { (const float*)d_in[7],  (const float*)d_in[11] };
    const float* g2b[2] = { (const float*)d_in[8],  (const float*)d_in[12] };
    float* out = (float*)d_out;

    __half *wh, *aA, *aB;
    cudaGetSymbolAddress((void**)&wh, g_wh);
    cudaGetSymbolAddress((void**)&aA, g_aA);
    cudaGetSymbolAddress((void**)&aB, g_aB);

    const size_t OW1 = 0, OW2 = 8388608;
    const size_t OG[4] = { 16777216, 50331648, 83886080, 117440512 };

    // driver entry point (no -lcuda link dependency)
    PFN_encodeTiled enc = nullptr;
    cudaDriverEntryPointQueryResult qr;
    cudaGetDriverEntryPointByVersion("cuTensorMapEncodeTiled", (void**)&enc,
                                     12000, cudaEnableDefault, &qr);

    // tensormaps (host-side, rebuilt each call; deterministic)
    CUtensorMap tm_aB = mk2d(enc, aB,        2048, 16384);
    CUtensorMap tm_aA = mk2d(enc, aA,        4096, 16384);
    CUtensorMap tm_w1 = mk2d(enc, wh + OW1,  2048, 4096);
    CUtensorMap tm_w2 = mk2d(enc, wh + OW2,  4096, 2048);
    CUtensorMap tm_g1[2] = { mk2d(enc, wh + OG[0], 2048, 16384),
                             mk2d(enc, wh + OG[2], 2048, 16384) };
    CUtensorMap tm_g2[2] = { mk2d(enc, wh + OG[1], 4096, 8192),
                             mk2d(enc, wh + OG[3], 4096, 8192) };

    cudaFuncSetAttribute(gemm1p, cudaFuncAttributeMaxDynamicSharedMemorySize, SMEM_SZ);

    auto conv = [&](const float* src, __half* dst, size_t n) {
        int n4 = (int)(n / 4);
        conv_h<<<(n4 + 255) / 256, 256>>>((const float4*)src, dst, n4);
    };

    const int Mg = T_TOK / 4;
    dim3 blk(256);

    conv(x,      aB,         (size_t)T_TOK * HID);
    conv(w1,     wh + OW1,   (size_t)IMM * HID);
    conv(w2,     wh + OW2,   (size_t)HID * IMM);
    conv(g1w[0], wh + OG[0], (size_t)4 * IMM * HID);
    conv(g2w[0], wh + OG[1], (size_t)4 * HID * IMM);

    // x @ w1^T -> actA  [16384, 4096]
    gemm1p<<<dim3(IMM / BN, T_TOK / BM, 1), blk, SMEM_SZ>>>(
        tm_aB, tm_w1, b1, nullptr, aA, T_TOK, IMM, HID, 0);

    conv(g1w[1], wh + OG[2], (size_t)4 * IMM * HID);
    conv(g2w[1], wh + OG[3], (size_t)4 * HID * IMM);

    // actA @ w2^T -> actB  [16384, 2048]
    gemm1p<<<dim3(HID / BN, T_TOK / BM, 1), blk, SMEM_SZ>>>(
        tm_aA, tm_w2, b2, nullptr, aB, T_TOK, HID, IMM, 0);
    // two grouped-MLP layers
    for (int li = 0; li < 2; li++) {
        gemm1p<<<dim3(IMM / BN, Mg / BM, 4), blk, SMEM_SZ>>>(
            tm_aB, tm_g1[li], g1b[li], nullptr, aA, Mg, IMM, HID, 0);
        int fin = (li == 1);
        gemm1p<<<dim3(HID / BN, Mg / BM, 4), blk, SMEM_SZ>>>(
            tm_aA, tm_g2[li], g2b[li],
            fin ? out : nullptr, aB, Mg, HID, IMM, fin);
    }
}